// round 16
// baseline (speedup 1.0000x reference)
#include <cuda_runtime.h>
#include <stdint.h>
#include <math.h>

#define NTOK (32*3200)     // 102400 tokens
#define DM   512
#define NVOC 100
#define WTOT ((size_t)256*262144)
#define F2   254.f         // second-digit radix
#define F2INV 0.003937007874015748f   // 1/254

// ---------------------------------------------------------------------------
// Scratch (device globals; allocation-free per harness rules).
// ---------------------------------------------------------------------------
__device__ int8_t g_xt1[128*DM];               // quantized embedding table
__device__ int8_t g_xt2[128*DM];
__device__ float  g_sxt[128];
__device__ float  g_qt[4*128*DM];              // per-level q/k/v tables
__device__ float  g_kt[4*128*DM];
__device__ float  g_vt[4*128*DM];
__device__ float  g_mv[4*128];                 // per-level vocab row-max of vt
__device__ float  g_E [4*NVOC*8*128];          // per-level exp tables
__device__ int8_t g_o1[(size_t)4*NTOK*DM];     // per-level quantized merged(o)
__device__ int8_t g_o2[(size_t)4*NTOK*DM];
__device__ float  g_sa[4*8192];                // per-level per-window scales
__device__ int8_t g_wo1[4*512*512];            // per-level row-quantized Wo
__device__ int8_t g_wo2[4*512*512];
__device__ float  g_swo[4*512];
__device__ float  g_wf[(size_t)240*262144];    // per-level fused Wf fp32
__device__ int8_t g_f1[(size_t)240*262144];    // per-level quantized Wf^T
__device__ int8_t g_f2[(size_t)240*262144];
__device__ float  g_swf[4*512];
__device__ float  g_S [4*512*512];             // per-level sum_r Wp_r
__device__ float  g_bf[4*512];                 // per-level fused bias
__device__ float  g_part[(size_t)4*NTOK*64];   // per-level split-K partials
__device__ int8_t g_w1[WTOT];
__device__ int8_t g_w2[WTOT];
__device__ float  g_sw[10240];                 // attn scales + pm scales

// ---------------------------------------------------------------------------
// Streams/events created once at load time.
// ---------------------------------------------------------------------------
namespace {
struct Streams {
    cudaStream_t st[8];
    cudaEvent_t root;
    cudaEvent_t evA;        // embed done
    cudaEvent_t wprep[4];
    cudaEvent_t done[4];
    Streams() {
        for (int i = 0; i < 8; i++)
            cudaStreamCreateWithFlags(&st[i], cudaStreamNonBlocking);
        for (int i = 0; i < 4; i++) {
            cudaEventCreateWithFlags(&wprep[i], cudaEventDisableTiming);
            cudaEventCreateWithFlags(&done[i], cudaEventDisableTiming);
        }
        cudaEventCreateWithFlags(&root, cudaEventDisableTiming);
        cudaEventCreateWithFlags(&evA, cudaEventDisableTiming);
    }
};
Streams g_sx;
}

// ---------------------------------------------------------------------------
// Helpers
// ---------------------------------------------------------------------------
__device__ __forceinline__ uint32_t smem_u32(const void* p) {
    uint32_t a;
    asm("{ .reg .u64 t; cvta.to.shared.u64 t, %1; cvt.u32.u64 %0, t; }"
        : "=r"(a) : "l"(p));
    return a;
}
__device__ __forceinline__ void cp16(uint32_t dst, const void* src, bool pred) {
    int sz = pred ? 16 : 0;
    asm volatile("cp.async.cg.shared.global [%0], [%1], 16, %2;"
                 :: "r"(dst), "l"(src), "r"(sz) : "memory");
}
__device__ __forceinline__ void cp_commit() {
    asm volatile("cp.async.commit_group;" ::: "memory");
}
__device__ __forceinline__ void cp_wait1() {
    asm volatile("cp.async.wait_group 1;" ::: "memory");
}
__device__ __forceinline__ void ldsm4(uint32_t* r, uint32_t addr) {
    asm volatile("ldmatrix.sync.aligned.m8n8.x4.shared.b16 {%0,%1,%2,%3}, [%4];"
                 : "=r"(r[0]), "=r"(r[1]), "=r"(r[2]), "=r"(r[3]) : "r"(addr));
}
__device__ __forceinline__ void mma_s8(int* d, const uint32_t* a, const uint32_t* b) {
    asm volatile(
        "mma.sync.aligned.m16n8k32.row.col.s32.s8.s8.s32 "
        "{%0,%1,%2,%3}, {%4,%5,%6,%7}, {%8,%9}, {%0,%1,%2,%3};"
        : "+r"(d[0]), "+r"(d[1]), "+r"(d[2]), "+r"(d[3])
        : "r"(a[0]), "r"(a[1]), "r"(a[2]), "r"(a[3]), "r"(b[0]), "r"(b[1]));
}

// ---------------------------------------------------------------------------
// Embedding TABLE quantization (100 vocab rows). Warp per vocab row.
// ---------------------------------------------------------------------------
__global__ __launch_bounds__(256)
void embed_quant(const float* __restrict__ emb) {
    int wid = threadIdx.x >> 5, lane = threadIdx.x & 31;
    int t = blockIdx.x * 8 + wid;
    if (t >= NVOC) return;
    const float4* e = (const float4*)(emb + (size_t)t * DM + lane * 16);
    float4 q0 = e[0], q1 = e[1], q2 = e[2], q3 = e[3];
    const float s = 22.62741699796952f;
    float f[16] = {q0.x*s,q0.y*s,q0.z*s,q0.w*s, q1.x*s,q1.y*s,q1.z*s,q1.w*s,
                   q2.x*s,q2.y*s,q2.z*s,q2.w*s, q3.x*s,q3.y*s,q3.z*s,q3.w*s};
    float mx = 0.f;
#pragma unroll
    for (int i = 0; i < 16; i++) mx = fmaxf(mx, fabsf(f[i]));
#pragma unroll
    for (int o = 16; o; o >>= 1) mx = fmaxf(mx, __shfl_xor_sync(~0u, mx, o));
    float sc = fmaxf(mx, 1e-20f) * (1.f / 127.f);
    float inv = 1.f / sc;
    char c1[16], c2[16];
#pragma unroll
    for (int i = 0; i < 16; i++) {
        int ia = __float2int_rn(f[i] * inv);
        float r = f[i] - (float)ia * sc;
        int ib = __float2int_rn(r * inv * F2);
        c1[i] = (char)ia; c2[i] = (char)ib;
    }
    size_t off = (size_t)t * DM + lane * 16;
    *(uint4*)(g_xt1 + off) = *(uint4*)c1;
    *(uint4*)(g_xt2 + off) = *(uint4*)c2;
    if (lane == 0) g_sxt[t] = sc;
}

// ---------------------------------------------------------------------------
// Fused attn-weight scale + transpose + 2-digit quantize.
// One level per launch: W points at 4 contiguous 512x512 mats; grid (16,4).
// ---------------------------------------------------------------------------
__global__ __launch_bounds__(256)
void wconv_attn(const float* __restrict__ W, int8_t* __restrict__ T1,
                int8_t* __restrict__ T2, float* __restrict__ sw) {
    __shared__ float t[32][33];
    __shared__ float cmax[8][32];
    __shared__ float scs[32];
    int z = blockIdx.y;
    const float* Wm = W + (size_t)z * 262144;
    int nb = blockIdx.x * 32;
    int tx = threadIdx.x & 31, ty = threadIdx.x >> 5;
    float m = 0.f;
    for (int k = ty; k < 512; k += 8)
        m = fmaxf(m, fabsf(Wm[(size_t)k * 512 + nb + tx]));
    cmax[ty][tx] = m;
    __syncthreads();
    if (ty == 0) {
        float mm = cmax[0][tx];
#pragma unroll
        for (int j = 1; j < 8; j++) mm = fmaxf(mm, cmax[j][tx]);
        float s0 = fmaxf(mm, 1e-20f) * (1.f / 127.f);
        scs[tx] = s0;
        sw[z * 512 + nb + tx] = s0;
    }
    __syncthreads();
    for (int kb = 0; kb < 512; kb += 32) {
        for (int i = ty; i < 32; i += 8)
            t[i][tx] = Wm[(size_t)(kb + i) * 512 + nb + tx];
        __syncthreads();
        for (int i = ty; i < 32; i += 8) {
            float v = t[tx][i];
            float s0 = scs[i];
            float inv = 1.f / s0;
            int ia = __float2int_rn(v * inv);
            float r = v - (float)ia * s0;
            int ib = __float2int_rn(r * inv * F2);
            size_t o = (size_t)z * 262144 + (size_t)(nb + i) * 512 + kb + tx;
            T1[o] = (int8_t)ia; T2[o] = (int8_t)ib;
        }
        __syncthreads();
    }
}

// ---------------------------------------------------------------------------
// Score-exp table: E[v1][h][v2] = exp(qt[v1]·kt[v2]/8 - rowmax(v1,h)).
// ---------------------------------------------------------------------------
__global__ __launch_bounds__(128)
void score_exp(const float* __restrict__ qt, const float* __restrict__ kt,
               float* __restrict__ E) {
    __shared__ float red[128];
    const int v1 = blockIdx.x, h = blockIdx.y;
    const int tid = threadIdx.x;
    float acc = 0.f;
    float s = -1e30f;
    if (tid < NVOC) {
        const float* qr = qt + (size_t)v1 * DM + h * 64;
        const float* kr = kt + (size_t)tid * DM + h * 64;
#pragma unroll 16
        for (int d = 0; d < 64; d++) acc += qr[d] * kr[d];
        acc *= 0.125f;
        s = acc;
    }
    red[tid] = s; __syncthreads();
    for (int st = 64; st; st >>= 1) {
        if (tid < st) red[tid] = fmaxf(red[tid], red[tid + st]);
        __syncthreads();
    }
    float m = red[0];
    E[((size_t)v1 * 8 + h) * 128 + tid] = (tid < NVOC) ? __expf(acc - m) : 0.f;
}

// ---------------------------------------------------------------------------
// vocab_max: mv[v] = max_d |vt[v][d]|.  Warp per vocab row.
// ---------------------------------------------------------------------------
__global__ __launch_bounds__(256)
void vocab_max(const float* __restrict__ vt, float* __restrict__ mv) {
    int wid = threadIdx.x >> 5, lane = threadIdx.x & 31;
    int v = blockIdx.x * 8 + wid;
    if (v >= 128) return;
    float m = 0.f;
    if (v < NVOC)
        for (int d = lane; d < DM; d += 32) m = fmaxf(m, fabsf(vt[v * DM + d]));
#pragma unroll
    for (int o = 16; o; o >>= 1) m = fmaxf(m, __shfl_xor_sync(~0u, m, o));
    if (lane == 0) mv[v] = m;
}

// ---------------------------------------------------------------------------
// window_scale: sa[m] = max over window tokens of mv[spec] / 127.
// ---------------------------------------------------------------------------
__global__ void window_scale(const int* __restrict__ spec,
                             const float* __restrict__ mv,
                             float* __restrict__ sa, int win, int M2) {
    int m = blockIdx.x * 256 + threadIdx.x;
    if (m >= M2) return;
    float mx = 0.f;
    const int* sp = spec + (size_t)m * win;
    for (int t = 0; t < win; t++) mx = fmaxf(mx, mv[sp[t]]);
    sa[m] = fmaxf(mx, 1e-20f) * (1.f / 127.f);
}

// ---------------------------------------------------------------------------
// Per-row (512-wide) 2-digit quantization (used for Wo rows).
// ---------------------------------------------------------------------------
__global__ __launch_bounds__(256)
void quant_rows(const float* __restrict__ src, int8_t* __restrict__ d1,
                int8_t* __restrict__ d2, float* __restrict__ sc) {
    int wid = threadIdx.x >> 5, lane = threadIdx.x & 31;
    int t = blockIdx.x * 8 + wid;
    const float4* e = (const float4*)(src + (size_t)t * DM + lane * 16);
    float4 q0 = e[0], q1 = e[1], q2 = e[2], q3 = e[3];
    float f[16] = {q0.x,q0.y,q0.z,q0.w, q1.x,q1.y,q1.z,q1.w,
                   q2.x,q2.y,q2.z,q2.w, q3.x,q3.y,q3.z,q3.w};
    float mx = 0.f;
#pragma unroll
    for (int i = 0; i < 16; i++) mx = fmaxf(mx, fabsf(f[i]));
#pragma unroll
    for (int o = 16; o; o >>= 1) mx = fmaxf(mx, __shfl_xor_sync(~0u, mx, o));
    float s0 = fmaxf(mx, 1e-20f) * (1.f / 127.f);
    float inv = 1.f / s0;
    char c1[16], c2[16];
#pragma unroll
    for (int i = 0; i < 16; i++) {
        int ia = __float2int_rn(f[i] * inv);
        float r = f[i] - (float)ia * s0;
        int ib = __float2int_rn(r * inv * F2);
        c1[i] = (char)ia; c2[i] = (char)ib;
    }
    size_t off = (size_t)t * DM + lane * 16;
    *(uint4*)(d1 + off) = *(uint4*)c1;
    *(uint4*)(d2 + off) = *(uint4*)c2;
    if (lane == 0) sc[t] = s0;
}

// ---------------------------------------------------------------------------
// Weight scale/quant utility kernels
// ---------------------------------------------------------------------------
__global__ void zero_sw(unsigned* sw) { sw[blockIdx.x * 256 + threadIdx.x] = 0u; }
__global__ void finalize_sw(float* sw) {
    int i = blockIdx.x * 256 + threadIdx.x;
    sw[i] = fmaxf(sw[i], 1e-20f) * (1.f / 127.f);
}
__global__ void colmax_kernel(const float* __restrict__ W, unsigned* __restrict__ sw,
                              int K, int rows_per) {
    int n = blockIdx.x * 256 + threadIdx.x;
    int k0 = blockIdx.y * rows_per;
    int k1 = min(k0 + rows_per, K);
    float m = 0.f;
    for (int k = k0; k < k1; k++) m = fmaxf(m, fabsf(W[(size_t)k * 512 + n]));
    atomicMax(&sw[n], __float_as_uint(m));
}

__global__ __launch_bounds__(256)
void wconv_q(const float* __restrict__ W, int8_t* __restrict__ T1,
             int8_t* __restrict__ T2, const float* __restrict__ sw, int K) {
    __shared__ float t[32][33];
    int kb = blockIdx.x * 32, nb = blockIdx.y * 32;
    int tx = threadIdx.x & 31, ty = threadIdx.x >> 5;
    for (int i = ty; i < 32; i += 8)
        t[i][tx] = W[(size_t)(kb + i) * 512 + nb + tx];
    __syncthreads();
    for (int i = ty; i < 32; i += 8) {
        float v = t[tx][i];
        int n = nb + i;
        float s0 = sw[n];
        float inv = 1.f / s0;
        int ia = __float2int_rn(v * inv);
        float r = v - (float)ia * s0;
        int ib = __float2int_rn(r * inv * F2);
        size_t o = (size_t)n * K + kb + tx;
        T1[o] = (int8_t)ia; T2[o] = (int8_t)ib;
    }
}

// ---------------------------------------------------------------------------
// Bias fusion: S[c][n] = sum_r Wp[r*512+c][n];  bf[n] = bp[n] + sum_c bo[c]*S.
// ---------------------------------------------------------------------------
__global__ void sum_wp(const float* __restrict__ Wp, float* __restrict__ S, int win) {
    int idx = blockIdx.x * 256 + threadIdx.x;   // 512*512
    int c = idx >> 9, n = idx & 511;
    float s = 0.f;
    for (int r = 0; r < win; r++)
        s += Wp[((size_t)(r * 512 + c)) * 512 + n];
    S[idx] = s;
}
__global__ void bias_fuse(const float* __restrict__ bo, const float* __restrict__ S,
                          const float* __restrict__ bp, float* __restrict__ bf) {
    int n = blockIdx.x * 256 + threadIdx.x;
    float s = bp[n];
    for (int c = 0; c < 512; c++) s += bo[c] * S[c * 512 + n];
    bf[n] = s;
}

// ---------------------------------------------------------------------------
// IMMA 2-digit int8 GEMM. C = sA*sB*(acc1 + acc2/254) (+ bias).
// mode 3: split-K stacked fp32 store, sA[gm]
// mode 4: fused QKV (N=1536) with bias
// ---------------------------------------------------------------------------
#define RSB   144
#define TILEB (128*RSB)
#define STGB  (4*TILEB)
#define OA1 0
#define OA2 TILEB
#define OB1 (2*TILEB)
#define OB2 (3*TILEB)
#define NSTAGE 3
#define GEMM_SMEM (NSTAGE*STGB)   // 221184

__global__ __launch_bounds__(512)
void imma_gemm(const int8_t* __restrict__ A1, const int8_t* __restrict__ A2,
               const int8_t* __restrict__ B1, const int8_t* __restrict__ B2,
               const float* __restrict__ sA, const float* __restrict__ sB,
               const float* __restrict__ bias,
               float* __restrict__ C0, float* __restrict__ C1, float* __restrict__ C2,
               int M, int K, int strideA, int aLocal, int Kslc, int mode)
{
    extern __shared__ __align__(128) char smem[];
    const uint32_t sb = smem_u32(smem);
    const int tid = threadIdx.x, wid = tid >> 5, lane = tid & 31;
    const int m0 = blockIdx.y * 128, n0 = blockIdx.x * 128;
    const int kbase = blockIdx.z * Kslc;
    const int wm = (wid & 3) * 32;
    const int wn = (wid >> 2) * 32;

    int acc1[2][4][4], acc2[2][4][4];
#pragma unroll
    for (int i = 0; i < 2; i++)
#pragma unroll
        for (int j = 0; j < 4; j++)
#pragma unroll
            for (int r = 0; r < 4; r++) { acc1[i][j][r] = 0; acc2[i][j][r] = 0; }

    const int nch = Kslc >> 7;

    auto load_stage = [&](int s, int c) {
        const int k0 = kbase + (c << 7);
        const int kA = aLocal ? (c << 7) : k0;
        const uint32_t stg = sb + s * STGB;
#pragma unroll
        for (int j = 0; j < 2; j++) {
            const int idx = tid + (j << 9);
            const int row = idx >> 3;
            const int c16 = idx & 7;
            const uint32_t so = row * RSB + (c16 << 4);
            const bool p = (m0 + row) < M;
            const size_t gA = (size_t)(m0 + row) * strideA + kA + (c16 << 4);
            cp16(stg + OA1 + so, A1 + (p ? gA : 0), p);
            cp16(stg + OA2 + so, A2 + (p ? gA : 0), p);
            const size_t gB = (size_t)(n0 + row) * K + k0 + (c16 << 4);
            cp16(stg + OB1 + so, B1 + gB, true);
            cp16(stg + OB2 + so, B2 + gB, true);
        }
    };

    load_stage(0, 0); cp_commit();
    if (nch > 1) load_stage(1, 1);
    cp_commit();

    const uint32_t a_lane = (uint32_t)(lane & 15) * RSB + (uint32_t)(lane >> 4) * 16;
    const uint32_t b_lane = (uint32_t)((lane & 7) + ((lane >> 4) << 3)) * RSB
                          + (uint32_t)((lane >> 3) & 1) * 16;

    int stage = 0;
    for (int c = 0; c < nch; c++) {
        cp_wait1();
        __syncthreads();

        const int pf = c + 2;
        if (pf < nch) {
            int ps = stage + 2; if (ps >= NSTAGE) ps -= NSTAGE;
            load_stage(ps, pf);
        }
        cp_commit();

        const uint32_t stg = sb + stage * STGB;
        const uint32_t a1Base = stg + OA1 + wm * RSB + a_lane;
        const uint32_t a2Base = stg + OA2 + wm * RSB + a_lane;
        const uint32_t b1Base = stg + OB1 + wn * RSB + b_lane;
        const uint32_t b2Base = stg + OB2 + wn * RSB + b_lane;

#pragma unroll
        for (int ks = 0; ks < 4; ks++) {
            const uint32_t koff = ks * 32;
            uint32_t a1f[2][4], a2f[2][4], b1f[2][4], b2f[2][4];
#pragma unroll
            for (int ma = 0; ma < 2; ma++) {
                ldsm4(a1f[ma], a1Base + ma * (16 * RSB) + koff);
                ldsm4(a2f[ma], a2Base + ma * (16 * RSB) + koff);
            }
#pragma unroll
            for (int nb = 0; nb < 2; nb++) {
                ldsm4(b1f[nb], b1Base + nb * (16 * RSB) + koff);
                ldsm4(b2f[nb], b2Base + nb * (16 * RSB) + koff);
            }
#pragma unroll
            for (int ma = 0; ma < 2; ma++)
#pragma unroll
                for (int na = 0; na < 4; na++)
                    mma_s8(acc1[ma][na], a1f[ma], &b1f[na >> 1][(na & 1) * 2]);
#pragma unroll
            for (int ma = 0; ma < 2; ma++)
#pragma unroll
                for (int na = 0; na < 4; na++)
                    mma_s8(acc2[ma][na], a1f[ma], &b2f[na >> 1][(na & 1) * 2]);
#pragma unroll
            for (int ma = 0; ma < 2; ma++)
#pragma unroll
                for (int na = 0; na < 4; na++)
                    mma_s8(acc2[ma][na], a2f[ma], &b1f[na >> 1][(na & 1) * 2]);
        }
        stage++; if (stage == NSTAGE) stage = 0;
    }

    const int mrow = lane >> 2;
    const int ncol = (lane & 3) * 2;
    float* tgt = C0;
    if (mode == 4) {
        int mi = n0 >> 9;
        tgt = (mi == 0) ? C0 : ((mi == 1) ? C1 : C2);
    }
    const bool splitk = (mode == 3);
#pragma unroll
    for (int ma = 0; ma < 2; ma++) {
#pragma unroll
        for (int half = 0; half < 2; half++) {
            int gm = m0 + wm + ma * 16 + mrow + half * 8;
            if (gm >= M) continue;
            float sa = sA[gm];
            size_t rowbase = splitk
                ? ((size_t)blockIdx.z * (size_t)M + gm) * 512
                : (size_t)gm * 512;
#pragma unroll
            for (int na = 0; na < 4; na++) {
                int gn = n0 + wn + na * 8 + ncol;
                int i0 = half * 2, i1 = half * 2 + 1;
                float f0 = (float)acc1[ma][na][i0] + (float)acc2[ma][na][i0] * F2INV;
                float f1 = (float)acc1[ma][na][i1] + (float)acc2[ma][na][i1] * F2INV;
                float v0 = sa * sB[gn]     * f0;
                float v1 = sa * sB[gn + 1] * f1;
                if (!splitk) { v0 += bias[gn]; v1 += bias[gn + 1]; }
                int col = (mode == 4) ? (gn & 511) : gn;
                *(float2*)(tgt + rowbase + col) = make_float2(v0, v1);
            }
        }
    }
}

// ---------------------------------------------------------------------------
// Split-K reduce + fused bias + scatter into output concat.
// ---------------------------------------------------------------------------
__global__ void reduce_scatter(const float* __restrict__ part,
                               const float* __restrict__ bias,
                               float* __restrict__ out,
                               int M, int splits, int rpb, int roff) {
    int idx = blockIdx.x * blockDim.x + threadIdx.x;
    if (idx >= M * 128) return;
    int m = idx >> 7;
    int n = (idx & 127) << 2;
    float4 s = *(const float4*)(bias + n);
    size_t stride = (size_t)M * 512;
    const float* p = part + (size_t)m * 512 + n;
    for (int z = 0; z < splits; z++) {
        float4 v = *(const float4*)(p + z * stride);
        s.x += v.x; s.y += v.y; s.z += v.z; s.w += v.w;
    }
    long crow = (long)(m / rpb) * 375 + (m % rpb) + roff;
    *(float4*)(out + crow * 512 + n) = s;
}

// ---------------------------------------------------------------------------
// Windowed attention via precomputed E-table + inline int8 quantization
// (per-window conservative scale sap[blockIdx.x]).
// ---------------------------------------------------------------------------
__global__ __launch_bounds__(256)
void attn_kernel(int win, const int* __restrict__ spec,
                 const float* __restrict__ E, const float* __restrict__ vt,
                 int8_t* __restrict__ d1, int8_t* __restrict__ d2,
                 const float* __restrict__ sap) {
    __shared__ float sc[8 * 128];
    __shared__ int vids[128];

    const int w = blockIdx.x, h = blockIdx.y;
    const int tok0 = w * win;
    const int tid = threadIdx.x;
    const int wid = tid >> 5, lane = tid & 31;
    const float s0 = sap[w];
    const float qinv = 1.f / s0;

    if (tid < win) vids[tid] = spec[tok0 + tid];
    __syncthreads();

    for (int r = wid; r < win; r += 8) {
        const int u = vids[r];
        const float* Erow = E + ((size_t)u * 8 + h) * 128;
        float loc[4];
        float sum = 0.f;
        int cnt = 0;
        for (int kk = lane; kk < win; kk += 32) {
            float e = Erow[vids[kk]];
            loc[cnt++] = e;
            sum += e;
        }
#pragma unroll
        for (int o = 16; o; o >>= 1) sum += __shfl_xor_sync(~0u, sum, o);
        float inv = 1.f / sum;
        for (int j = 0; j < cnt; j++) sc[wid * win + lane + 32 * j] = loc[j] * inv;
        __syncwarp();

        float o0 = 0.f, o1 = 0.f;
        for (int kk = 0; kk < win; kk++) {
            float p = sc[wid * win + kk];
            const float2 vv = *(const float2*)(vt + (size_t)vids[kk] * DM
                                               + h * 64 + 2 * lane);
            o0 += p * vv.x;
            o1 += p * vv.y;
        }
        int ia0 = __float2int_rn(o0 * qinv);
        float r0 = o0 - (float)ia0 * s0;
        int ib0 = __float2int_rn(r0 * qinv * F2);
        int ia1 = __float2int_rn(o1 * qinv);
        float r1 = o1 - (float)ia1 * s0;
        int ib1 = __float2int_rn(r1 * qinv * F2);
        size_t ob = (size_t)(tok0 + r) * DM + h * 64 + 2 * lane;
        char2 c1; c1.x = (char)ia0; c1.y = (char)ia1;
        char2 c2; c2.x = (char)ib0; c2.y = (char)ib1;
        *(char2*)(d1 + ob) = c1;
        *(char2*)(d2 + ob) = c2;
        __syncwarp();
    }
}

// ---------------------------------------------------------------------------
// Launch: early fork. Stream 0: embed only (evA). Per level: weight-prep
// chain on stream i+4; attn chain (incl. its own wconv_attn) on stream i.
// ---------------------------------------------------------------------------
extern "C" void kernel_launch(void* const* d_in, const int* in_sizes, int n_in,
                              void* d_out, int out_size) {
    const int*   spec   = (const int*)d_in[0];
    const float* emb    = (const float*)d_in[1];
    const float* attn_w = (const float*)d_in[2];
    const float* attn_b = (const float*)d_in[3];
    const float* pw[4]  = {(const float*)d_in[4], (const float*)d_in[6],
                           (const float*)d_in[8], (const float*)d_in[10]};
    const float* pb[4]  = {(const float*)d_in[5], (const float*)d_in[7],
                           (const float*)d_in[9], (const float*)d_in[11]};
    float* out = (float*)d_out;

    int8_t *xt1, *xt2, *o1, *o2, *wo1, *wo2, *f1, *f2, *w1, *w2;
    float *sxt, *sa, *swo, *swf, *sw, *qt, *kt, *vt, *mv, *part, *E, *wf, *S, *bf;
    cudaGetSymbolAddress((void**)&xt1, g_xt1);
    cudaGetSymbolAddress((void**)&xt2, g_xt2);
    cudaGetSymbolAddress((void**)&sxt, g_sxt);
    cudaGetSymbolAddress((void**)&qt,  g_qt);
    cudaGetSymbolAddress((void**)&kt,  g_kt);
    cudaGetSymbolAddress((void**)&vt,  g_vt);
    cudaGetSymbolAddress((void**)&mv,  g_mv);
    cudaGetSymbolAddress((void**)&E,   g_E);
    cudaGetSymbolAddress((void**)&o1,  g_o1);
    cudaGetSymbolAddress((void**)&o2,  g_o2);
    cudaGetSymbolAddress((void**)&sa,  g_sa);
    cudaGetSymbolAddress((void**)&wo1, g_wo1);
    cudaGetSymbolAddress((void**)&wo2, g_wo2);
    cudaGetSymbolAddress((void**)&swo, g_swo);
    cudaGetSymbolAddress((void**)&wf,  g_wf);
    cudaGetSymbolAddress((void**)&f1,  g_f1);
    cudaGetSymbolAddress((void**)&f2,  g_f2);
    cudaGetSymbolAddress((void**)&swf, g_swf);
    cudaGetSymbolAddress((void**)&S,   g_S);
    cudaGetSymbolAddress((void**)&bf,  g_bf);
    cudaGetSymbolAddress((void**)&part,g_part);
    cudaGetSymbolAddress((void**)&w1,  g_w1);
    cudaGetSymbolAddress((void**)&w2,  g_w2);
    cudaGetSymbolAddress((void**)&sw,  g_sw);

    cudaFuncSetAttribute(imma_gemm, cudaFuncAttributeMaxDynamicSharedMemorySize,
                         GEMM_SMEM);

    const int wins[4] = {16, 32, 64, 128};
    const int offs[4] = {0, 200, 300, 350};
    const size_t pwoff[4] = {4194304ull, 8388608ull, 16777216ull, 33554432ull};
    const size_t wfoff[4] = {0ull, 16ull*262144, 48ull*262144, 112ull*262144};

    // ---- fork immediately ----
    cudaEventRecord(g_sx.root, 0);
    for (int i = 0; i < 8; i++)
        cudaStreamWaitEvent(g_sx.st[i], g_sx.root, 0);

    // ---- stream 0: embedding table quant ----
    embed_quant<<<13, 256>>>(emb);
    cudaEventRecord(g_sx.evA, 0);

    for (int i = 0; i < 4; i++) {
        cudaStream_t sA = g_sx.st[i];       // attention + PM chain
        cudaStream_t sW = g_sx.st[i + 4];   // weight-prep chain
        const int win = wins[i];
        const int Kfull = win * 512;
        size_t wbase = (size_t)i * 4 * 262144;
        const float* Bb = attn_b + (size_t)i * 2048;
        const float* Wo = attn_w + wbase + 3 * 262144;

        float*  qtL = qt + (size_t)i * 128 * DM;
        float*  ktL = kt + (size_t)i * 128 * DM;
        float*  vtL = vt + (size_t)i * 128 * DM;
        float*  mvL = mv + (size_t)i * 128;
        float*  EL  = E  + (size_t)i * NVOC * 8 * 128;
        int8_t* o1L = o1 + (size_t)i * NTOK * DM;
        int8_t* o2L = o2 + (size_t)i * NTOK * DM;
        float*  saL = sa + (size_t)i * 8192;
        int8_t* wo1L = wo1 + (size_t)i * 262144;
        int8_t* wo2L = wo2 + (size_t)i * 262144;
        float*  swoL = swo + (size_t)i * 512;
        float*  wfL = wf + wfoff[i];
        int8_t* f1L = f1 + wfoff[i];
        int8_t* f2L = f2 + wfoff[i];
        float*  swfL = swf + (size_t)i * 512;
        float*  SL  = S  + (size_t)i * 262144;
        float*  bfL = bf + (size_t)i * 512;
        float*  partL = part + (size_t)i * NTOK * 64;
        float*  swpL = sw + 8192 + (size_t)i * 512;

        // ---- weight-prep chain (stream sW), starts immediately ----
        zero_sw<<<2, 256, 0, sW>>>((unsigned*)swpL);
        colmax_kernel<<<dim3(2, Kfull / 128), 256, 0, sW>>>(pw[i],
            (unsigned*)swpL, Kfull, 128);
        finalize_sw<<<2, 256, 0, sW>>>(swpL);
        wconv_q<<<dim3(Kfull / 32, 16), 256, 0, sW>>>(pw[i], w1 + pwoff[i],
            w2 + pwoff[i], swpL, Kfull);
        quant_rows<<<64, 256, 0, sW>>>(Wo, wo1L, wo2L, swoL);
        imma_gemm<<<dim3(4, 4, win), 512, GEMM_SMEM, sW>>>(
            wo1L, wo2L, w1 + pwoff[i], w2 + pwoff[i], swoL, swpL,
            nullptr, wfL, nullptr, nullptr, 512, Kfull, 512, 1, 512, 3);
        zero_sw<<<2, 256, 0, sW>>>((unsigned*)swfL);
        colmax_kernel<<<dim3(2, Kfull / 128), 256, 0, sW>>>(wfL,
            (unsigned*)swfL, Kfull, 128);
        finalize_sw<<<2, 256, 0, sW>>>(swfL);
        wconv_q<<<dim3(Kfull / 32, 16), 256, 0, sW>>>(wfL, f1L, f2L, swfL, Kfull);
        sum_wp<<<1024, 256, 0, sW>>>(pw[i], SL, win);
        bias_fuse<<<2, 256, 0, sW>>>(Bb + 1536, SL, pb[i], bfL);
        cudaEventRecord(g_sx.wprep[i], sW);

        // ---- attention chain (stream sA): own attn-weight quant first ----
        cudaStreamWaitEvent(sA, g_sx.evA, 0);
        wconv_attn<<<dim3(16, 4), 256, 0, sA>>>(attn_w + wbase, w1 + wbase,
                                                w2 + wbase, sw + i * 2048);
        imma_gemm<<<dim3(12, 1, 1), 512, GEMM_SMEM, sA>>>(
            xt1, xt2, w1 + wbase, w2 + wbase, sxt, sw + i * 2048, Bb,
            qtL, ktL, vtL, NVOC, 512, 512, 0, 512, 4);
        score_exp<<<dim3(NVOC, 8), 128, 0, sA>>>(qtL, ktL, EL);
        vocab_max<<<16, 256, 0, sA>>>(vtL, mvL);
        const int rpb = 3200 / win;
        const int M2  = 32 * rpb;
        window_scale<<<(M2 + 255) / 256, 256, 0, sA>>>(spec, mvL, saL, win, M2);
        attn_kernel<<<dim3(NTOK / win, 8), 256, 0, sA>>>(win, spec, EL, vtL,
                                                         o1L, o2L, saL);

        // ---- join weight prep, then PM GEMM + reduce (stream sA) ----
        cudaStreamWaitEvent(sA, g_sx.wprep[i], 0);
        const int KSLC = 4096;
        const int splits = Kfull / KSLC;   // win/8: 2,4,8,16
        dim3 g2(4, (M2 + 127) / 128, splits);
        imma_gemm<<<g2, 512, GEMM_SMEM, sA>>>(o1L, o2L, f1L, f2L, saL, swfL,
                                              nullptr, partL, nullptr, nullptr,
                                              M2, Kfull, Kfull, 0, KSLC, 3);
        int nthr = M2 * 128;
        reduce_scatter<<<(nthr + 255) / 256, 256, 0, sA>>>(partL, bfL, out,
                                                           M2, splits, rpb, offs[i]);
        cudaEventRecord(g_sx.done[i], sA);
    }

    // ---- join back to stream 0 ----
    for (int i = 0; i < 4; i++)
        cudaStreamWaitEvent(0, g_sx.done[i], 0);
}

// round 17
// speedup vs baseline: 1.0340x; 1.0340x over previous
#include <cuda_runtime.h>
#include <stdint.h>
#include <math.h>

#define NTOK (32*3200)     // 102400 tokens
#define DM   512
#define NVOC 100
#define WTOT ((size_t)256*262144)
#define F2   254.f         // second-digit radix
#define F2INV 0.003937007874015748f   // 1/254

// ---------------------------------------------------------------------------
// Scratch (device globals; allocation-free per harness rules).
// ---------------------------------------------------------------------------
__device__ int8_t g_xt1[128*DM];               // quantized embedding table
__device__ int8_t g_xt2[128*DM];
__device__ float  g_sxt[128];
__device__ float  g_qt[4*128*DM];              // per-level q/k/v tables
__device__ float  g_kt[4*128*DM];
__device__ float  g_vt[4*128*DM];
__device__ float  g_mv[4*128];                 // per-level vocab row-max of vt
__device__ float  g_E [4*NVOC*8*128];          // per-level exp tables
__device__ int8_t g_o1[(size_t)4*NTOK*DM];     // per-level quantized merged(o)
__device__ int8_t g_o2[(size_t)4*NTOK*DM];
__device__ float  g_sa[4*8192];                // per-level per-window scales
__device__ int8_t g_wo1[4*512*512];            // per-level row-quantized Wo
__device__ int8_t g_wo2[4*512*512];
__device__ float  g_swo[4*512];
__device__ float  g_wf[(size_t)240*262144];    // per-level fused Wf fp32
__device__ int8_t g_f1[(size_t)240*262144];    // per-level quantized Wf^T
__device__ int8_t g_f2[(size_t)240*262144];
__device__ float  g_swf[4*512];
__device__ float  g_S [4*512*512];             // per-level sum_r Wp_r
__device__ float  g_bf[4*512];                 // per-level fused bias
__device__ float  g_part[(size_t)4*NTOK*64];   // per-level split-K partials
__device__ int8_t g_w1[WTOT];
__device__ int8_t g_w2[WTOT];
__device__ float  g_sw[10240];                 // attn scales + pm scales

// ---------------------------------------------------------------------------
// Streams/events created once at load time.
// ---------------------------------------------------------------------------
namespace {
struct Streams {
    cudaStream_t st[8];
    cudaEvent_t root;
    cudaEvent_t evA;        // embed done
    cudaEvent_t wprep[4];
    cudaEvent_t done[4];
    Streams() {
        for (int i = 0; i < 8; i++)
            cudaStreamCreateWithFlags(&st[i], cudaStreamNonBlocking);
        for (int i = 0; i < 4; i++) {
            cudaEventCreateWithFlags(&wprep[i], cudaEventDisableTiming);
            cudaEventCreateWithFlags(&done[i], cudaEventDisableTiming);
        }
        cudaEventCreateWithFlags(&root, cudaEventDisableTiming);
        cudaEventCreateWithFlags(&evA, cudaEventDisableTiming);
    }
};
Streams g_sx;
}

// ---------------------------------------------------------------------------
// Helpers
// ---------------------------------------------------------------------------
__device__ __forceinline__ uint32_t smem_u32(const void* p) {
    uint32_t a;
    asm("{ .reg .u64 t; cvta.to.shared.u64 t, %1; cvt.u32.u64 %0, t; }"
        : "=r"(a) : "l"(p));
    return a;
}
__device__ __forceinline__ void cp16(uint32_t dst, const void* src, bool pred) {
    int sz = pred ? 16 : 0;
    asm volatile("cp.async.cg.shared.global [%0], [%1], 16, %2;"
                 :: "r"(dst), "l"(src), "r"(sz) : "memory");
}
__device__ __forceinline__ void cp_commit() {
    asm volatile("cp.async.commit_group;" ::: "memory");
}
__device__ __forceinline__ void cp_wait1() {
    asm volatile("cp.async.wait_group 1;" ::: "memory");
}
__device__ __forceinline__ void ldsm4(uint32_t* r, uint32_t addr) {
    asm volatile("ldmatrix.sync.aligned.m8n8.x4.shared.b16 {%0,%1,%2,%3}, [%4];"
                 : "=r"(r[0]), "=r"(r[1]), "=r"(r[2]), "=r"(r[3]) : "r"(addr));
}
__device__ __forceinline__ void mma_s8(int* d, const uint32_t* a, const uint32_t* b) {
    asm volatile(
        "mma.sync.aligned.m16n8k32.row.col.s32.s8.s8.s32 "
        "{%0,%1,%2,%3}, {%4,%5,%6,%7}, {%8,%9}, {%0,%1,%2,%3};"
        : "+r"(d[0]), "+r"(d[1]), "+r"(d[2]), "+r"(d[3])
        : "r"(a[0]), "r"(a[1]), "r"(a[2]), "r"(a[3]), "r"(b[0]), "r"(b[1]));
}

// ---------------------------------------------------------------------------
// Embedding TABLE quantization (100 vocab rows). Warp per vocab row.
// ---------------------------------------------------------------------------
__global__ __launch_bounds__(256)
void embed_quant(const float* __restrict__ emb) {
    int wid = threadIdx.x >> 5, lane = threadIdx.x & 31;
    int t = blockIdx.x * 8 + wid;
    if (t >= NVOC) return;
    const float4* e = (const float4*)(emb + (size_t)t * DM + lane * 16);
    float4 q0 = e[0], q1 = e[1], q2 = e[2], q3 = e[3];
    const float s = 22.62741699796952f;
    float f[16] = {q0.x*s,q0.y*s,q0.z*s,q0.w*s, q1.x*s,q1.y*s,q1.z*s,q1.w*s,
                   q2.x*s,q2.y*s,q2.z*s,q2.w*s, q3.x*s,q3.y*s,q3.z*s,q3.w*s};
    float mx = 0.f;
#pragma unroll
    for (int i = 0; i < 16; i++) mx = fmaxf(mx, fabsf(f[i]));
#pragma unroll
    for (int o = 16; o; o >>= 1) mx = fmaxf(mx, __shfl_xor_sync(~0u, mx, o));
    float sc = fmaxf(mx, 1e-20f) * (1.f / 127.f);
    float inv = 1.f / sc;
    char c1[16], c2[16];
#pragma unroll
    for (int i = 0; i < 16; i++) {
        int ia = __float2int_rn(f[i] * inv);
        float r = f[i] - (float)ia * sc;
        int ib = __float2int_rn(r * inv * F2);
        c1[i] = (char)ia; c2[i] = (char)ib;
    }
    size_t off = (size_t)t * DM + lane * 16;
    *(uint4*)(g_xt1 + off) = *(uint4*)c1;
    *(uint4*)(g_xt2 + off) = *(uint4*)c2;
    if (lane == 0) g_sxt[t] = sc;
}

// ---------------------------------------------------------------------------
// Fused attn-weight scale + transpose + 2-digit quantize.
// One level per launch: W points at 4 contiguous 512x512 mats; grid (16,4).
// ---------------------------------------------------------------------------
__global__ __launch_bounds__(256)
void wconv_attn(const float* __restrict__ W, int8_t* __restrict__ T1,
                int8_t* __restrict__ T2, float* __restrict__ sw) {
    __shared__ float t[32][33];
    __shared__ float cmax[8][32];
    __shared__ float scs[32];
    int z = blockIdx.y;
    const float* Wm = W + (size_t)z * 262144;
    int nb = blockIdx.x * 32;
    int tx = threadIdx.x & 31, ty = threadIdx.x >> 5;
    float m = 0.f;
    for (int k = ty; k < 512; k += 8)
        m = fmaxf(m, fabsf(Wm[(size_t)k * 512 + nb + tx]));
    cmax[ty][tx] = m;
    __syncthreads();
    if (ty == 0) {
        float mm = cmax[0][tx];
#pragma unroll
        for (int j = 1; j < 8; j++) mm = fmaxf(mm, cmax[j][tx]);
        float s0 = fmaxf(mm, 1e-20f) * (1.f / 127.f);
        scs[tx] = s0;
        sw[z * 512 + nb + tx] = s0;
    }
    __syncthreads();
    for (int kb = 0; kb < 512; kb += 32) {
        for (int i = ty; i < 32; i += 8)
            t[i][tx] = Wm[(size_t)(kb + i) * 512 + nb + tx];
        __syncthreads();
        for (int i = ty; i < 32; i += 8) {
            float v = t[tx][i];
            float s0 = scs[i];
            float inv = 1.f / s0;
            int ia = __float2int_rn(v * inv);
            float r = v - (float)ia * s0;
            int ib = __float2int_rn(r * inv * F2);
            size_t o = (size_t)z * 262144 + (size_t)(nb + i) * 512 + kb + tx;
            T1[o] = (int8_t)ia; T2[o] = (int8_t)ib;
        }
        __syncthreads();
    }
}

// ---------------------------------------------------------------------------
// Score-exp table: E[v1][h][v2] = exp(qt[v1]·kt[v2]/8 - rowmax(v1,h)).
// ---------------------------------------------------------------------------
__global__ __launch_bounds__(128)
void score_exp(const float* __restrict__ qt, const float* __restrict__ kt,
               float* __restrict__ E) {
    __shared__ float red[128];
    const int v1 = blockIdx.x, h = blockIdx.y;
    const int tid = threadIdx.x;
    float acc = 0.f;
    float s = -1e30f;
    if (tid < NVOC) {
        const float* qr = qt + (size_t)v1 * DM + h * 64;
        const float* kr = kt + (size_t)tid * DM + h * 64;
#pragma unroll 16
        for (int d = 0; d < 64; d++) acc += qr[d] * kr[d];
        acc *= 0.125f;
        s = acc;
    }
    red[tid] = s; __syncthreads();
    for (int st = 64; st; st >>= 1) {
        if (tid < st) red[tid] = fmaxf(red[tid], red[tid + st]);
        __syncthreads();
    }
    float m = red[0];
    E[((size_t)v1 * 8 + h) * 128 + tid] = (tid < NVOC) ? __expf(acc - m) : 0.f;
}

// ---------------------------------------------------------------------------
// vocab_max: mv[v] = max_d |vt[v][d]|.  Warp per vocab row.
// ---------------------------------------------------------------------------
__global__ __launch_bounds__(256)
void vocab_max(const float* __restrict__ vt, float* __restrict__ mv) {
    int wid = threadIdx.x >> 5, lane = threadIdx.x & 31;
    int v = blockIdx.x * 8 + wid;
    if (v >= 128) return;
    float m = 0.f;
    if (v < NVOC)
        for (int d = lane; d < DM; d += 32) m = fmaxf(m, fabsf(vt[v * DM + d]));
#pragma unroll
    for (int o = 16; o; o >>= 1) m = fmaxf(m, __shfl_xor_sync(~0u, m, o));
    if (lane == 0) mv[v] = m;
}

// ---------------------------------------------------------------------------
// window_scale: sa[m] = max over window tokens of mv[spec] / 127.
// ---------------------------------------------------------------------------
__global__ void window_scale(const int* __restrict__ spec,
                             const float* __restrict__ mv,
                             float* __restrict__ sa, int win, int M2) {
    int m = blockIdx.x * 256 + threadIdx.x;
    if (m >= M2) return;
    float mx = 0.f;
    const int* sp = spec + (size_t)m * win;
    for (int t = 0; t < win; t++) mx = fmaxf(mx, mv[sp[t]]);
    sa[m] = fmaxf(mx, 1e-20f) * (1.f / 127.f);
}

// ---------------------------------------------------------------------------
// Per-row (512-wide) 2-digit quantization (used for Wo rows).
// ---------------------------------------------------------------------------
__global__ __launch_bounds__(256)
void quant_rows(const float* __restrict__ src, int8_t* __restrict__ d1,
                int8_t* __restrict__ d2, float* __restrict__ sc) {
    int wid = threadIdx.x >> 5, lane = threadIdx.x & 31;
    int t = blockIdx.x * 8 + wid;
    const float4* e = (const float4*)(src + (size_t)t * DM + lane * 16);
    float4 q0 = e[0], q1 = e[1], q2 = e[2], q3 = e[3];
    float f[16] = {q0.x,q0.y,q0.z,q0.w, q1.x,q1.y,q1.z,q1.w,
                   q2.x,q2.y,q2.z,q2.w, q3.x,q3.y,q3.z,q3.w};
    float mx = 0.f;
#pragma unroll
    for (int i = 0; i < 16; i++) mx = fmaxf(mx, fabsf(f[i]));
#pragma unroll
    for (int o = 16; o; o >>= 1) mx = fmaxf(mx, __shfl_xor_sync(~0u, mx, o));
    float s0 = fmaxf(mx, 1e-20f) * (1.f / 127.f);
    float inv = 1.f / s0;
    char c1[16], c2[16];
#pragma unroll
    for (int i = 0; i < 16; i++) {
        int ia = __float2int_rn(f[i] * inv);
        float r = f[i] - (float)ia * s0;
        int ib = __float2int_rn(r * inv * F2);
        c1[i] = (char)ia; c2[i] = (char)ib;
    }
    size_t off = (size_t)t * DM + lane * 16;
    *(uint4*)(d1 + off) = *(uint4*)c1;
    *(uint4*)(d2 + off) = *(uint4*)c2;
    if (lane == 0) sc[t] = s0;
}

// ---------------------------------------------------------------------------
// Weight scale/quant utility kernels
// ---------------------------------------------------------------------------
__global__ void zero_sw(unsigned* sw) { sw[blockIdx.x * 256 + threadIdx.x] = 0u; }
__global__ void finalize_sw(float* sw) {
    int i = blockIdx.x * 256 + threadIdx.x;
    sw[i] = fmaxf(sw[i], 1e-20f) * (1.f / 127.f);
}
__global__ void colmax_kernel(const float* __restrict__ W, unsigned* __restrict__ sw,
                              int K, int rows_per) {
    int n = blockIdx.x * 256 + threadIdx.x;
    int k0 = blockIdx.y * rows_per;
    int k1 = min(k0 + rows_per, K);
    float m = 0.f;
    for (int k = k0; k < k1; k++) m = fmaxf(m, fabsf(W[(size_t)k * 512 + n]));
    atomicMax(&sw[n], __float_as_uint(m));
}

__global__ __launch_bounds__(256)
void wconv_q(const float* __restrict__ W, int8_t* __restrict__ T1,
             int8_t* __restrict__ T2, const float* __restrict__ sw, int K) {
    __shared__ float t[32][33];
    int kb = blockIdx.x * 32, nb = blockIdx.y * 32;
    int tx = threadIdx.x & 31, ty = threadIdx.x >> 5;
    for (int i = ty; i < 32; i += 8)
        t[i][tx] = W[(size_t)(kb + i) * 512 + nb + tx];
    __syncthreads();
    for (int i = ty; i < 32; i += 8) {
        float v = t[tx][i];
        int n = nb + i;
        float s0 = sw[n];
        float inv = 1.f / s0;
        int ia = __float2int_rn(v * inv);
        float r = v - (float)ia * s0;
        int ib = __float2int_rn(r * inv * F2);
        size_t o = (size_t)n * K + kb + tx;
        T1[o] = (int8_t)ia; T2[o] = (int8_t)ib;
    }
}

// ---------------------------------------------------------------------------
// Bias fusion: S[c][n] = sum_r Wp[r*512+c][n];  bf[n] = bp[n] + sum_c bo[c]*S.
// ---------------------------------------------------------------------------
__global__ void sum_wp(const float* __restrict__ Wp, float* __restrict__ S, int win) {
    int idx = blockIdx.x * 256 + threadIdx.x;   // 512*512
    int c = idx >> 9, n = idx & 511;
    float s = 0.f;
    for (int r = 0; r < win; r++)
        s += Wp[((size_t)(r * 512 + c)) * 512 + n];
    S[idx] = s;
}
__global__ void bias_fuse(const float* __restrict__ bo, const float* __restrict__ S,
                          const float* __restrict__ bp, float* __restrict__ bf) {
    int n = blockIdx.x * 256 + threadIdx.x;
    float s = bp[n];
    for (int c = 0; c < 512; c++) s += bo[c] * S[c * 512 + n];
    bf[n] = s;
}

// ---------------------------------------------------------------------------
// IMMA 2-digit int8 GEMM. C = sA*sB*(acc1 + acc2/254) (+ bias).
// mode 3: split-K stacked fp32 store, sA[gm]
// mode 4: fused QKV (N=1536) with bias
// ---------------------------------------------------------------------------
#define RSB   144
#define TILEB (128*RSB)
#define STGB  (4*TILEB)
#define OA1 0
#define OA2 TILEB
#define OB1 (2*TILEB)
#define OB2 (3*TILEB)
#define NSTAGE 3
#define GEMM_SMEM (NSTAGE*STGB)   // 221184

__global__ __launch_bounds__(512)
void imma_gemm(const int8_t* __restrict__ A1, const int8_t* __restrict__ A2,
               const int8_t* __restrict__ B1, const int8_t* __restrict__ B2,
               const float* __restrict__ sA, const float* __restrict__ sB,
               const float* __restrict__ bias,
               float* __restrict__ C0, float* __restrict__ C1, float* __restrict__ C2,
               int M, int K, int strideA, int aLocal, int Kslc, int mode)
{
    extern __shared__ __align__(128) char smem[];
    const uint32_t sb = smem_u32(smem);
    const int tid = threadIdx.x, wid = tid >> 5, lane = tid & 31;
    const int m0 = blockIdx.y * 128, n0 = blockIdx.x * 128;
    const int kbase = blockIdx.z * Kslc;
    const int wm = (wid & 3) * 32;
    const int wn = (wid >> 2) * 32;

    int acc1[2][4][4], acc2[2][4][4];
#pragma unroll
    for (int i = 0; i < 2; i++)
#pragma unroll
        for (int j = 0; j < 4; j++)
#pragma unroll
            for (int r = 0; r < 4; r++) { acc1[i][j][r] = 0; acc2[i][j][r] = 0; }

    const int nch = Kslc >> 7;

    auto load_stage = [&](int s, int c) {
        const int k0 = kbase + (c << 7);
        const int kA = aLocal ? (c << 7) : k0;
        const uint32_t stg = sb + s * STGB;
#pragma unroll
        for (int j = 0; j < 2; j++) {
            const int idx = tid + (j << 9);
            const int row = idx >> 3;
            const int c16 = idx & 7;
            const uint32_t so = row * RSB + (c16 << 4);
            const bool p = (m0 + row) < M;
            const size_t gA = (size_t)(m0 + row) * strideA + kA + (c16 << 4);
            cp16(stg + OA1 + so, A1 + (p ? gA : 0), p);
            cp16(stg + OA2 + so, A2 + (p ? gA : 0), p);
            const size_t gB = (size_t)(n0 + row) * K + k0 + (c16 << 4);
            cp16(stg + OB1 + so, B1 + gB, true);
            cp16(stg + OB2 + so, B2 + gB, true);
        }
    };

    load_stage(0, 0); cp_commit();
    if (nch > 1) load_stage(1, 1);
    cp_commit();

    const uint32_t a_lane = (uint32_t)(lane & 15) * RSB + (uint32_t)(lane >> 4) * 16;
    const uint32_t b_lane = (uint32_t)((lane & 7) + ((lane >> 4) << 3)) * RSB
                          + (uint32_t)((lane >> 3) & 1) * 16;

    int stage = 0;
    for (int c = 0; c < nch; c++) {
        cp_wait1();
        __syncthreads();

        const int pf = c + 2;
        if (pf < nch) {
            int ps = stage + 2; if (ps >= NSTAGE) ps -= NSTAGE;
            load_stage(ps, pf);
        }
        cp_commit();

        const uint32_t stg = sb + stage * STGB;
        const uint32_t a1Base = stg + OA1 + wm * RSB + a_lane;
        const uint32_t a2Base = stg + OA2 + wm * RSB + a_lane;
        const uint32_t b1Base = stg + OB1 + wn * RSB + b_lane;
        const uint32_t b2Base = stg + OB2 + wn * RSB + b_lane;

#pragma unroll
        for (int ks = 0; ks < 4; ks++) {
            const uint32_t koff = ks * 32;
            uint32_t a1f[2][4], a2f[2][4], b1f[2][4], b2f[2][4];
#pragma unroll
            for (int ma = 0; ma < 2; ma++) {
                ldsm4(a1f[ma], a1Base + ma * (16 * RSB) + koff);
                ldsm4(a2f[ma], a2Base + ma * (16 * RSB) + koff);
            }
#pragma unroll
            for (int nb = 0; nb < 2; nb++) {
                ldsm4(b1f[nb], b1Base + nb * (16 * RSB) + koff);
                ldsm4(b2f[nb], b2Base + nb * (16 * RSB) + koff);
            }
#pragma unroll
            for (int ma = 0; ma < 2; ma++)
#pragma unroll
                for (int na = 0; na < 4; na++)
                    mma_s8(acc1[ma][na], a1f[ma], &b1f[na >> 1][(na & 1) * 2]);
#pragma unroll
            for (int ma = 0; ma < 2; ma++)
#pragma unroll
                for (int na = 0; na < 4; na++)
                    mma_s8(acc2[ma][na], a1f[ma], &b2f[na >> 1][(na & 1) * 2]);
#pragma unroll
            for (int ma = 0; ma < 2; ma++)
#pragma unroll
                for (int na = 0; na < 4; na++)
                    mma_s8(acc2[ma][na], a2f[ma], &b1f[na >> 1][(na & 1) * 2]);
        }
        stage++; if (stage == NSTAGE) stage = 0;
    }

    const int mrow = lane >> 2;
    const int ncol = (lane & 3) * 2;
    float* tgt = C0;
    if (mode == 4) {
        int mi = n0 >> 9;
        tgt = (mi == 0) ? C0 : ((mi == 1) ? C1 : C2);
    }
    const bool splitk = (mode == 3);
#pragma unroll
    for (int ma = 0; ma < 2; ma++) {
#pragma unroll
        for (int half = 0; half < 2; half++) {
            int gm = m0 + wm + ma * 16 + mrow + half * 8;
            if (gm >= M) continue;
            float sa = sA[gm];
            size_t rowbase = splitk
                ? ((size_t)blockIdx.z * (size_t)M + gm) * 512
                : (size_t)gm * 512;
#pragma unroll
            for (int na = 0; na < 4; na++) {
                int gn = n0 + wn + na * 8 + ncol;
                int i0 = half * 2, i1 = half * 2 + 1;
                float f0 = (float)acc1[ma][na][i0] + (float)acc2[ma][na][i0] * F2INV;
                float f1 = (float)acc1[ma][na][i1] + (float)acc2[ma][na][i1] * F2INV;
                float v0 = sa * sB[gn]     * f0;
                float v1 = sa * sB[gn + 1] * f1;
                if (!splitk) { v0 += bias[gn]; v1 += bias[gn + 1]; }
                int col = (mode == 4) ? (gn & 511) : gn;
                *(float2*)(tgt + rowbase + col) = make_float2(v0, v1);
            }
        }
    }
}

// ---------------------------------------------------------------------------
// Split-K reduce + fused bias + scatter into output concat.
// ---------------------------------------------------------------------------
__global__ void reduce_scatter(const float* __restrict__ part,
                               const float* __restrict__ bias,
                               float* __restrict__ out,
                               int M, int splits, int rpb, int roff) {
    int idx = blockIdx.x * blockDim.x + threadIdx.x;
    if (idx >= M * 128) return;
    int m = idx >> 7;
    int n = (idx & 127) << 2;
    float4 s = *(const float4*)(bias + n);
    size_t stride = (size_t)M * 512;
    const float* p = part + (size_t)m * 512 + n;
    for (int z = 0; z < splits; z++) {
        float4 v = *(const float4*)(p + z * stride);
        s.x += v.x; s.y += v.y; s.z += v.z; s.w += v.w;
    }
    long crow = (long)(m / rpb) * 375 + (m % rpb) + roff;
    *(float4*)(out + crow * 512 + n) = s;
}

// ---------------------------------------------------------------------------
// Windowed attention (win >= 64): block per (window, head), 8 warps.
// E-table gather + inline int8 quantization.
// ---------------------------------------------------------------------------
__global__ __launch_bounds__(256)
void attn_kernel(int win, const int* __restrict__ spec,
                 const float* __restrict__ E, const float* __restrict__ vt,
                 int8_t* __restrict__ d1, int8_t* __restrict__ d2,
                 const float* __restrict__ sap) {
    __shared__ float sc[8 * 128];
    __shared__ int vids[128];

    const int w = blockIdx.x, h = blockIdx.y;
    const int tok0 = w * win;
    const int tid = threadIdx.x;
    const int wid = tid >> 5, lane = tid & 31;
    const float s0 = sap[w];
    const float qinv = 1.f / s0;

    if (tid < win) vids[tid] = spec[tok0 + tid];
    __syncthreads();

    for (int r = wid; r < win; r += 8) {
        const int u = vids[r];
        const float* Erow = E + ((size_t)u * 8 + h) * 128;
        float loc[4];
        float sum = 0.f;
        int cnt = 0;
        for (int kk = lane; kk < win; kk += 32) {
            float e = Erow[vids[kk]];
            loc[cnt++] = e;
            sum += e;
        }
#pragma unroll
        for (int o = 16; o; o >>= 1) sum += __shfl_xor_sync(~0u, sum, o);
        float inv = 1.f / sum;
        for (int j = 0; j < cnt; j++) sc[wid * win + lane + 32 * j] = loc[j] * inv;
        __syncwarp();

        float o0 = 0.f, o1 = 0.f;
        for (int kk = 0; kk < win; kk++) {
            float p = sc[wid * win + kk];
            const float2 vv = *(const float2*)(vt + (size_t)vids[kk] * DM
                                               + h * 64 + 2 * lane);
            o0 += p * vv.x;
            o1 += p * vv.y;
        }
        int ia0 = __float2int_rn(o0 * qinv);
        float r0 = o0 - (float)ia0 * s0;
        int ib0 = __float2int_rn(r0 * qinv * F2);
        int ia1 = __float2int_rn(o1 * qinv);
        float r1 = o1 - (float)ia1 * s0;
        int ib1 = __float2int_rn(r1 * qinv * F2);
        size_t ob = (size_t)(tok0 + r) * DM + h * 64 + 2 * lane;
        char2 c1; c1.x = (char)ia0; c1.y = (char)ia1;
        char2 c2; c2.x = (char)ib0; c2.y = (char)ib1;
        *(char2*)(d1 + ob) = c1;
        *(char2*)(d2 + ob) = c2;
        __syncwarp();
    }
}

// ---------------------------------------------------------------------------
// Windowed attention (win <= 32): block per WINDOW (all 8 heads),
// warp = head, warp serially processes all rows. Same math/order as
// attn_kernel => bit-identical output; 8x fewer blocks.
// ---------------------------------------------------------------------------
__global__ __launch_bounds__(256)
void attn_small(int win, const int* __restrict__ spec,
                const float* __restrict__ E, const float* __restrict__ vt,
                int8_t* __restrict__ d1, int8_t* __restrict__ d2,
                const float* __restrict__ sap) {
    __shared__ float sc[8][32];
    __shared__ int vids[32];

    const int w = blockIdx.x;
    const int tok0 = w * win;
    const int tid = threadIdx.x;
    const int h = tid >> 5, lane = tid & 31;   // warp = head
    const float s0 = sap[w];
    const float qinv = 1.f / s0;

    if (tid < win) vids[tid] = spec[tok0 + tid];
    __syncthreads();

    for (int r = 0; r < win; r++) {
        const int u = vids[r];
        const float* Erow = E + ((size_t)u * 8 + h) * 128;
        float e = (lane < win) ? Erow[vids[lane]] : 0.f;
        float sum = e;
#pragma unroll
        for (int o = 16; o; o >>= 1) sum += __shfl_xor_sync(~0u, sum, o);
        float inv = 1.f / sum;
        if (lane < win) sc[h][lane] = e * inv;
        __syncwarp();

        float o0 = 0.f, o1 = 0.f;
        for (int kk = 0; kk < win; kk++) {
            float p = sc[h][kk];
            const float2 vv = *(const float2*)(vt + (size_t)vids[kk] * DM
                                               + h * 64 + 2 * lane);
            o0 += p * vv.x;
            o1 += p * vv.y;
        }
        int ia0 = __float2int_rn(o0 * qinv);
        float r0 = o0 - (float)ia0 * s0;
        int ib0 = __float2int_rn(r0 * qinv * F2);
        int ia1 = __float2int_rn(o1 * qinv);
        float r1 = o1 - (float)ia1 * s0;
        int ib1 = __float2int_rn(r1 * qinv * F2);
        size_t ob = (size_t)(tok0 + r) * DM + h * 64 + 2 * lane;
        char2 c1; c1.x = (char)ia0; c1.y = (char)ia1;
        char2 c2; c2.x = (char)ib0; c2.y = (char)ib1;
        *(char2*)(d1 + ob) = c1;
        *(char2*)(d2 + ob) = c2;
        __syncwarp();
    }
}

// ---------------------------------------------------------------------------
// Launch: early fork. Stream 0: embed only (evA). Per level: weight-prep
// chain on stream i+4; attn chain (incl. its own wconv_attn) on stream i.
// ---------------------------------------------------------------------------
extern "C" void kernel_launch(void* const* d_in, const int* in_sizes, int n_in,
                              void* d_out, int out_size) {
    const int*   spec   = (const int*)d_in[0];
    const float* emb    = (const float*)d_in[1];
    const float* attn_w = (const float*)d_in[2];
    const float* attn_b = (const float*)d_in[3];
    const float* pw[4]  = {(const float*)d_in[4], (const float*)d_in[6],
                           (const float*)d_in[8], (const float*)d_in[10]};
    const float* pb[4]  = {(const float*)d_in[5], (const float*)d_in[7],
                           (const float*)d_in[9], (const float*)d_in[11]};
    float* out = (float*)d_out;

    int8_t *xt1, *xt2, *o1, *o2, *wo1, *wo2, *f1, *f2, *w1, *w2;
    float *sxt, *sa, *swo, *swf, *sw, *qt, *kt, *vt, *mv, *part, *E, *wf, *S, *bf;
    cudaGetSymbolAddress((void**)&xt1, g_xt1);
    cudaGetSymbolAddress((void**)&xt2, g_xt2);
    cudaGetSymbolAddress((void**)&sxt, g_sxt);
    cudaGetSymbolAddress((void**)&qt,  g_qt);
    cudaGetSymbolAddress((void**)&kt,  g_kt);
    cudaGetSymbolAddress((void**)&vt,  g_vt);
    cudaGetSymbolAddress((void**)&mv,  g_mv);
    cudaGetSymbolAddress((void**)&E,   g_E);
    cudaGetSymbolAddress((void**)&o1,  g_o1);
    cudaGetSymbolAddress((void**)&o2,  g_o2);
    cudaGetSymbolAddress((void**)&sa,  g_sa);
    cudaGetSymbolAddress((void**)&wo1, g_wo1);
    cudaGetSymbolAddress((void**)&wo2, g_wo2);
    cudaGetSymbolAddress((void**)&swo, g_swo);
    cudaGetSymbolAddress((void**)&wf,  g_wf);
    cudaGetSymbolAddress((void**)&f1,  g_f1);
    cudaGetSymbolAddress((void**)&f2,  g_f2);
    cudaGetSymbolAddress((void**)&swf, g_swf);
    cudaGetSymbolAddress((void**)&S,   g_S);
    cudaGetSymbolAddress((void**)&bf,  g_bf);
    cudaGetSymbolAddress((void**)&part,g_part);
    cudaGetSymbolAddress((void**)&w1,  g_w1);
    cudaGetSymbolAddress((void**)&w2,  g_w2);
    cudaGetSymbolAddress((void**)&sw,  g_sw);

    cudaFuncSetAttribute(imma_gemm, cudaFuncAttributeMaxDynamicSharedMemorySize,
                         GEMM_SMEM);

    const int wins[4] = {16, 32, 64, 128};
    const int offs[4] = {0, 200, 300, 350};
    const size_t pwoff[4] = {4194304ull, 8388608ull, 16777216ull, 33554432ull};
    const size_t wfoff[4] = {0ull, 16ull*262144, 48ull*262144, 112ull*262144};

    // ---- fork immediately ----
    cudaEventRecord(g_sx.root, 0);
    for (int i = 0; i < 8; i++)
        cudaStreamWaitEvent(g_sx.st[i], g_sx.root, 0);

    // ---- stream 0: embedding table quant ----
    embed_quant<<<13, 256>>>(emb);
    cudaEventRecord(g_sx.evA, 0);

    for (int i = 0; i < 4; i++) {
        cudaStream_t sA = g_sx.st[i];       // attention + PM chain
        cudaStream_t sW = g_sx.st[i + 4];   // weight-prep chain
        const int win = wins[i];
        const int Kfull = win * 512;
        size_t wbase = (size_t)i * 4 * 262144;
        const float* Bb = attn_b + (size_t)i * 2048;
        const float* Wo = attn_w + wbase + 3 * 262144;

        float*  qtL = qt + (size_t)i * 128 * DM;
        float*  ktL = kt + (size_t)i * 128 * DM;
        float*  vtL = vt + (size_t)i * 128 * DM;
        float*  mvL = mv + (size_t)i * 128;
        float*  EL  = E  + (size_t)i * NVOC * 8 * 128;
        int8_t* o1L = o1 + (size_t)i * NTOK * DM;
        int8_t* o2L = o2 + (size_t)i * NTOK * DM;
        float*  saL = sa + (size_t)i * 8192;
        int8_t* wo1L = wo1 + (size_t)i * 262144;
        int8_t* wo2L = wo2 + (size_t)i * 262144;
        float*  swoL = swo + (size_t)i * 512;
        float*  wfL = wf + wfoff[i];
        int8_t* f1L = f1 + wfoff[i];
        int8_t* f2L = f2 + wfoff[i];
        float*  swfL = swf + (size_t)i * 512;
        float*  SL  = S  + (size_t)i * 262144;
        float*  bfL = bf + (size_t)i * 512;
        float*  partL = part + (size_t)i * NTOK * 64;
        float*  swpL = sw + 8192 + (size_t)i * 512;

        // ---- weight-prep chain (stream sW), starts immediately ----
        zero_sw<<<2, 256, 0, sW>>>((unsigned*)swpL);
        colmax_kernel<<<dim3(2, Kfull / 128), 256, 0, sW>>>(pw[i],
            (unsigned*)swpL, Kfull, 128);
        finalize_sw<<<2, 256, 0, sW>>>(swpL);
        wconv_q<<<dim3(Kfull / 32, 16), 256, 0, sW>>>(pw[i], w1 + pwoff[i],
            w2 + pwoff[i], swpL, Kfull);
        quant_rows<<<64, 256, 0, sW>>>(Wo, wo1L, wo2L, swoL);
        imma_gemm<<<dim3(4, 4, win), 512, GEMM_SMEM, sW>>>(
            wo1L, wo2L, w1 + pwoff[i], w2 + pwoff[i], swoL, swpL,
            nullptr, wfL, nullptr, nullptr, 512, Kfull, 512, 1, 512, 3);
        zero_sw<<<2, 256, 0, sW>>>((unsigned*)swfL);
        colmax_kernel<<<dim3(2, Kfull / 128), 256, 0, sW>>>(wfL,
            (unsigned*)swfL, Kfull, 128);
        finalize_sw<<<2, 256, 0, sW>>>(swfL);
        wconv_q<<<dim3(Kfull / 32, 16), 256, 0, sW>>>(wfL, f1L, f2L, swfL, Kfull);
        sum_wp<<<1024, 256, 0, sW>>>(pw[i], SL, win);
        bias_fuse<<<2, 256, 0, sW>>>(Bb + 1536, SL, pb[i], bfL);
        cudaEventRecord(g_sx.wprep[i], sW);

        // ---- attention chain (stream sA): own attn-weight quant first ----
        cudaStreamWaitEvent(sA, g_sx.evA, 0);
        wconv_attn<<<dim3(16, 4), 256, 0, sA>>>(attn_w + wbase, w1 + wbase,
                                                w2 + wbase, sw + i * 2048);
        imma_gemm<<<dim3(12, 1, 1), 512, GEMM_SMEM, sA>>>(
            xt1, xt2, w1 + wbase, w2 + wbase, sxt, sw + i * 2048, Bb,
            qtL, ktL, vtL, NVOC, 512, 512, 0, 512, 4);
        score_exp<<<dim3(NVOC, 8), 128, 0, sA>>>(qtL, ktL, EL);
        vocab_max<<<16, 256, 0, sA>>>(vtL, mvL);
        const int rpb = 3200 / win;
        const int M2  = 32 * rpb;
        window_scale<<<(M2 + 255) / 256, 256, 0, sA>>>(spec, mvL, saL, win, M2);
        if (win <= 32)
            attn_small<<<NTOK / win, 256, 0, sA>>>(win, spec, EL, vtL,
                                                   o1L, o2L, saL);
        else
            attn_kernel<<<dim3(NTOK / win, 8), 256, 0, sA>>>(win, spec, EL, vtL,
                                                             o1L, o2L, saL);

        // ---- join weight prep, then PM GEMM + reduce (stream sA) ----
        cudaStreamWaitEvent(sA, g_sx.wprep[i], 0);
        const int KSLC = 4096;
        const int splits = Kfull / KSLC;   // win/8: 2,4,8,16
        dim3 g2(4, (M2 + 127) / 128, splits);
        imma_gemm<<<g2, 512, GEMM_SMEM, sA>>>(o1L, o2L, f1L, f2L, saL, swfL,
                                              nullptr, partL, nullptr, nullptr,
                                              M2, Kfull, Kfull, 0, KSLC, 3);
        int nthr = M2 * 128;
        reduce_scatter<<<(nthr + 255) / 256, 256, 0, sA>>>(partL, bfL, out,
                                                           M2, splits, rpb, offs[i]);
        cudaEventRecord(g_sx.done[i], sA);
    }

    // ---- join back to stream 0 ----
    for (int i = 0; i < 4; i++)
        cudaStreamWaitEvent(0, g_sx.done[i], 0);
}